// round 10
// baseline (speedup 1.0000x reference)
#include <cuda_runtime.h>
#include <cuda_bf16.h>
#include <cstdint>
#include <cstddef>

#define QL      64
#define BSZ     8
#define CACHE_L 64
#define CACHE_N 512
#define NHID    1024
#define TOPK    4

#define ATT_ELEMS (QL * BSZ * CACHE_N)   // 262144
#define IDX_ELEMS (TOPK * QL * BSZ)      // 2048
#define NITEM2    (CACHE_N / 4 * BSZ)    // 1024 items: (4-slot group, b)
#define GRID_P    148                    // persistent, 1 CTA/SM

// Q hi/lo bf16 scratch, layout [b][i][h]
__device__ __align__(16) __nv_bfloat16 g_qh[BSZ * QL * NHID];
__device__ __align__(16) __nv_bfloat16 g_ql[BSZ * QL * NHID];
// monotonic ticket barrier (never reset -> graph-replay safe)
__device__ unsigned int g_bar = 0;

// ---------------------------------------------------------------------------
__device__ __forceinline__ uint32_t smem_u32(const void* p) {
    uint32_t a;
    asm("{ .reg .u64 t; cvta.to.shared.u64 t, %1; cvt.u32.u64 %0, t; }"
        : "=r"(a) : "l"(p));
    return a;
}
__device__ __forceinline__ void cp_async16(uint32_t dst, const void* src) {
    asm volatile("cp.async.cg.shared.global [%0], [%1], 16;"
                 :: "r"(dst), "l"(src) : "memory");
}
__device__ __forceinline__ void cp_commit() {
    asm volatile("cp.async.commit_group;" ::: "memory");
}
template <int N>
__device__ __forceinline__ void cp_wait() {
    asm volatile("cp.async.wait_group %0;" :: "n"(N) : "memory");
}
__device__ __forceinline__ void ldm_x4(uint32_t& r0, uint32_t& r1,
                                       uint32_t& r2, uint32_t& r3, uint32_t a) {
    asm volatile("ldmatrix.sync.aligned.m8n8.x4.shared.b16 {%0,%1,%2,%3}, [%4];"
                 : "=r"(r0), "=r"(r1), "=r"(r2), "=r"(r3) : "r"(a));
}
__device__ __forceinline__ void mma16816(float* c, const uint32_t* a,
                                         const uint32_t* b) {
    asm volatile(
        "mma.sync.aligned.m16n8k16.row.col.f32.bf16.bf16.f32 "
        "{%0,%1,%2,%3}, {%4,%5,%6,%7}, {%8,%9}, {%0,%1,%2,%3};"
        : "+f"(c[0]), "+f"(c[1]), "+f"(c[2]), "+f"(c[3])
        : "r"(a[0]), "r"(a[1]), "r"(a[2]), "r"(a[3]), "r"(b[0]), "r"(b[1]));
}

// device-wide barrier for a co-resident 148-CTA grid
__device__ __forceinline__ void gbar() {
    __syncthreads();
    if (threadIdx.x == 0) {
        __threadfence();
        unsigned t = atomicAdd(&g_bar, 1u);
        unsigned target = (t / GRID_P + 1u) * GRID_P;
        while (*(volatile unsigned*)&g_bar < target) { }
        __threadfence();
    }
    __syncthreads();
}

// ---------------------------------------------------------------------------
// Fully fused persistent kernel:
//   phase 1: qprep (Q fp32 -> bf16 hi/lo split)
//   phase 2: split-bf16 3-term GEMM, M=256 (4 slots) per CTA, N=64, K=1024;
//            8 warps, warp tile 32x64 (A-dup=1, B traffic amortized over 2x M)
//   phase 3: softmax + top-4 (one warp per (ql,b) row)
// ---------------------------------------------------------------------------
#define A_STAGE 65536                  // 256 rows x 256B (64 fp32)
#define B_BASE  (2 * A_STAGE)          // 131072
#define B_STAGE 16384                  // hi 8KB + lo 8KB (64 rows x 128B)
#define SRED_OFF (B_BASE + 2 * B_STAGE)        // 163840
#define SMEM_TOTAL (SRED_OFF + 2048)           // 165888

__global__ void __launch_bounds__(256, 1)
cache_fused_kernel(const float* __restrict__ query,
                   const float* __restrict__ keys,
                   float* __restrict__ out, int write_idx) {
    extern __shared__ char smem[];
    const uint32_t sbase = smem_u32(smem);
    const int tid  = threadIdx.x;
    const int w    = tid >> 5;
    const int lane = tid & 31;
    const int bid  = blockIdx.x;

    // ================= phase 1: qprep ==================
    {
        const int NG = (BSZ * QL * NHID) / 4;        // 131072 granules
        #pragma unroll
        for (int r = 0; r < 4; r++) {
            int g = bid * 256 + tid + r * (GRID_P * 256);
            if (g < NG) {
                int idx = g * 4;
                float4 f = *(const float4*)(query + idx);
                int i  = idx >> 13;
                int bq = (idx >> 10) & 7;
                int hh = idx & 1023;
                int o = (bq * QL + i) * NHID + hh;
                uint32_t bx = __float_as_uint(f.x), by = __float_as_uint(f.y);
                uint32_t bz = __float_as_uint(f.z), bw = __float_as_uint(f.w);
                uint2 hi;
                hi.x = __byte_perm(bx, by, 0x7632);
                hi.y = __byte_perm(bz, bw, 0x7632);
                float r0 = f.x - __uint_as_float(bx & 0xffff0000u);
                float r1 = f.y - __uint_as_float(by & 0xffff0000u);
                float r2 = f.z - __uint_as_float(bz & 0xffff0000u);
                float r3 = f.w - __uint_as_float(bw & 0xffff0000u);
                uint2 lo;
                asm("cvt.rn.bf16x2.f32 %0, %1, %2;" : "=r"(lo.x) : "f"(r1), "f"(r0));
                asm("cvt.rn.bf16x2.f32 %0, %1, %2;" : "=r"(lo.y) : "f"(r3), "f"(r2));
                *(uint2*)(g_qh + o) = hi;
                *(uint2*)(g_ql + o) = lo;
            }
        }
    }
    gbar();

    // ================= phase 2: GEMM ==================
    // B cp.async constants (R5-proven)
    const int bkb   = (tid & 7) * 16;
    const int brow0 = tid >> 3;                   // 0..31
    const size_t boff = (size_t)brow0 * NHID + (tid & 7) * 8;

    // B ldmatrix lane pieces (R5-proven)
    const int lt    = lane >> 3;
    const int lrow  = ((lt & 2) << 2) + (lane & 7);
    const int lkoff = (lt & 1) << 3;

    // A fragment pieces: warp w owns rows [32w, 32w+32), mt in {0,1}
    const int afr = (lane >> 2);
    const int afk = (lane & 3) << 1;

    const int nit = (NITEM2 - 1 - bid) / GRID_P + 1;
    const int VCN = nit * 16;

    // stage virtual chunk vc into buffers (vc&1)
    auto stage = [&](int vc) {
        int il = vc >> 4;
        int g  = bid + GRID_P * il;
        if (g >= NITEM2) return;
        int kc = vc & 15;
        int st = vc & 1;
        int p4 = g & 127;           // 4-slot group
        int bb = g >> 7;
        // A: 256 rows x 64 fp32; thread tid owns row tid (16 granules)
        const float* sA = keys
            + ((size_t)(p4 * 4 + (tid >> 6)) * BSZ + bb) * (CACHE_L * NHID)
            + (size_t)(tid & 63) * NHID + (size_t)kc * 64;
        uint32_t dA = sbase + st * A_STAGE + (uint32_t)(tid * 256);
        #pragma unroll
        for (int j = 0; j < 16; j++)
            cp_async16(dA + (uint32_t)((j * 16) ^ ((tid & 7) << 5)), sA + j * 4);
        // B: bf16 hi/lo, 64 rows x 64 cols (R5 mapping)
        uint32_t dBb = sbase + B_BASE + st * B_STAGE;
        size_t bo = (size_t)bb * (QL * NHID) + boff + (size_t)kc * 64;
        #pragma unroll
        for (int j = 0; j < 4; j++) {
            int half = j >> 1;
            int row  = brow0 + (j & 1) * 32;
            const __nv_bfloat16* s = (half ? g_ql : g_qh)
                + bo + (size_t)(j & 1) * 32 * NHID;
            uint32_t d = dBb + half * 8192
                       + (uint32_t)(row * 128 + (bkb ^ ((row & 7) << 4)));
            cp_async16(d, s);
        }
    };

    float acc[2][8][4];

    stage(0); cp_commit();
    stage(1); cp_commit();

    #pragma unroll 1
    for (int vc = 0; vc < VCN; vc++) {
        cp_wait<1>();
        __syncthreads();

        const int kc = vc & 15;
        if (kc == 0) {
            #pragma unroll
            for (int mt = 0; mt < 2; mt++)
                #pragma unroll
                for (int nt = 0; nt < 8; nt++)
                    #pragma unroll
                    for (int c = 0; c < 4; c++) acc[mt][nt][c] = 0.0f;
        }

        const uint32_t bufB = sbase + B_BASE + (vc & 1) * B_STAGE;
        const char* baseA = smem + (vc & 1) * A_STAGE;

        #pragma unroll
        for (int ks2 = 0; ks2 < 4; ks2++) {
            // B fragments (hi + lo), 8 n-tiles — shared by both m-tiles
            uint32_t bh[8][2], bl[8][2];
            #pragma unroll
            for (int np = 0; np < 4; np++) {
                int row = 16 * np + lrow;
                uint32_t kb = (uint32_t)((ks2 * 16 + lkoff) * 2);
                uint32_t swo = (uint32_t)(row * 128 + (kb ^ ((row & 7) << 4)));
                ldm_x4(bh[2 * np][0], bh[2 * np][1],
                       bh[2 * np + 1][0], bh[2 * np + 1][1], bufB + swo);
                ldm_x4(bl[2 * np][0], bl[2 * np][1],
                       bl[2 * np + 1][0], bl[2 * np + 1][1],
                       bufB + 8192 + swo);
            }

            #pragma unroll
            for (int mt = 0; mt < 2; mt++) {
                // A fragment: LDS fp32 once, convert hi/lo in-register
                uint32_t ah[4], al[4];
                {
                    const int R = w * 32 + mt * 16 + afr;
                    const int kidx = ks2 * 16 + afk;
                    float2 f0 = *(const float2*)(baseA
                        + R * 256 + ((kidx * 4) ^ ((R & 7) << 5)));
                    float2 f1 = *(const float2*)(baseA
                        + (R + 8) * 256 + ((kidx * 4) ^ (((R + 8) & 7) << 5)));
                    float2 f2 = *(const float2*)(baseA
                        + R * 256 + (((kidx + 8) * 4) ^ ((R & 7) << 5)));
                    float2 f3 = *(const float2*)(baseA
                        + (R + 8) * 256 + (((kidx + 8) * 4) ^ (((R + 8) & 7) << 5)));
                    float2 fs[4] = {f0, f1, f2, f3};
                    #pragma unroll
                    for (int j = 0; j < 4; j++) {
                        uint32_t bx = __float_as_uint(fs[j].x);
                        uint32_t by = __float_as_uint(fs[j].y);
                        ah[j] = __byte_perm(bx, by, 0x7632);
                        float rx = fs[j].x - __uint_as_float(bx & 0xffff0000u);
                        float ry = fs[j].y - __uint_as_float(by & 0xffff0000u);
                        asm("cvt.rn.bf16x2.f32 %0, %1, %2;"
                            : "=r"(al[j]) : "f"(ry), "f"(rx));
                    }
                }
                #pragma unroll
                for (int nt = 0; nt < 8; nt++) {
                    mma16816(acc[mt][nt], ah, bh[nt]);
                    mma16816(acc[mt][nt], ah, bl[nt]);
                    mma16816(acc[mt][nt], al, bh[nt]);
                }
            }
        }
        __syncthreads();

        stage(vc + 2);
        cp_commit();

        // ---- item epilogue: max over tokens -> raw logits ----
        if (kc == 15) {
            const int g  = bid + GRID_P * (vc >> 4);
            const int n0 = (g & 127) * 4;
            const int bb = g >> 7;

            // warp w covers rows [32w,32w+32) -> one slot (w>>1), both mt tiles
            float vmax[8][2];
            #pragma unroll
            for (int nt = 0; nt < 8; nt++) {
                float v0 = fmaxf(fmaxf(acc[0][nt][0], acc[0][nt][2]),
                                 fmaxf(acc[1][nt][0], acc[1][nt][2]));
                float v1 = fmaxf(fmaxf(acc[0][nt][1], acc[0][nt][3]),
                                 fmaxf(acc[1][nt][1], acc[1][nt][3]));
                #pragma unroll
                for (int o = 4; o < 32; o <<= 1) {
                    v0 = fmaxf(v0, __shfl_xor_sync(0xffffffffu, v0, o));
                    v1 = fmaxf(v1, __shfl_xor_sync(0xffffffffu, v1, o));
                }
                vmax[nt][0] = v0; vmax[nt][1] = v1;
            }

            float* sred = (float*)(smem + SRED_OFF);   // 8 warps x 64 cols
            if (lane < 4) {
                #pragma unroll
                for (int nt = 0; nt < 8; nt++) {
                    sred[w * 64 + 8 * nt + 2 * lane]     = vmax[nt][0];
                    sred[w * 64 + 8 * nt + 2 * lane + 1] = vmax[nt][1];
                }
            }
            __syncthreads();

            // 256 threads: (slot, query) = (tid>>6, tid&63)
            {
                int i  = tid & 63;
                int sl = tid >> 6;          // 0..3
                float v = fmaxf(sred[(2 * sl + 0) * 64 + i],
                                sred[(2 * sl + 1) * 64 + i]);
                out[(size_t)i * (BSZ * CACHE_N) + (size_t)bb * CACHE_N
                    + n0 + sl] = v;
            }
        }
    }

    gbar();

    // ================= phase 3: softmax + top-4 ==================
    {
        const int gid = bid * 8 + w;        // 0..1183
        if (gid < QL * BSZ) {
            float* p = out + (size_t)gid * CACHE_N;
            float v[16];
            float m = -1e30f;
            #pragma unroll
            for (int j = 0; j < 16; j++) {
                v[j] = p[lane + 32 * j] * 0.03125f;   // THETA/sqrt(NHID)
                m = fmaxf(m, v[j]);
            }
            #pragma unroll
            for (int o = 16; o > 0; o >>= 1)
                m = fmaxf(m, __shfl_xor_sync(0xffffffffu, m, o));
            float sum = 0.0f;
            #pragma unroll
            for (int j = 0; j < 16; j++) { v[j] = expf(v[j] - m); sum += v[j]; }
            #pragma unroll
            for (int o = 16; o > 0; o >>= 1)
                sum += __shfl_xor_sync(0xffffffffu, sum, o);
            float inv = 1.0f / sum;
            #pragma unroll
            for (int j = 0; j < 16; j++) {
                v[j] *= inv;
                p[lane + 32 * j] = v[j];
            }
            if (write_idx) {
                float* oidx = out + ATT_ELEMS;
                #pragma unroll 1
                for (int k = 0; k < TOPK; k++) {
                    float bv = -1.0f; int bi = 0;
                    #pragma unroll
                    for (int j = 0; j < 16; j++) {
                        int ii = lane + 32 * j;
                        if (v[j] > bv) { bv = v[j]; bi = ii; }
                    }
                    #pragma unroll
                    for (int o = 16; o > 0; o >>= 1) {
                        float ov = __shfl_xor_sync(0xffffffffu, bv, o);
                        int   oi = __shfl_xor_sync(0xffffffffu, bi, o);
                        if (ov > bv || (ov == bv && oi < bi)) { bv = ov; bi = oi; }
                    }
                    if (lane == 0) oidx[k * (QL * BSZ) + gid] = (float)bi;
                    if ((bi & 31) == lane) v[bi >> 5] = -1.0f;
                }
            }
        }
    }
}

// ---------------------------------------------------------------------------
extern "C" void kernel_launch(void* const* d_in, const int* in_sizes, int n_in,
                              void* d_out, int out_size) {
    const float* a0 = (const float*)d_in[0];
    const float* a1 = (const float*)d_in[1];
    const float* query = a0;
    const float* keys  = a1;
    if (in_sizes[0] != QL * BSZ * NHID) { query = a1; keys = a0; }

    float* out = (float*)d_out;
    int write_idx = (out_size >= ATT_ELEMS + IDX_ELEMS) ? 1 : 0;

    cudaFuncSetAttribute(cache_fused_kernel,
                         cudaFuncAttributeMaxDynamicSharedMemorySize, SMEM_TOTAL);
    cache_fused_kernel<<<GRID_P, 256, SMEM_TOTAL>>>(query, keys, out, write_idx);
}